// round 14
// baseline (speedup 1.0000x reference)
#include <cuda_runtime.h>
#include <math.h>

#define LL 12
#define BB 8
#define HH 16
#define DD 64
#define EE 1024
#define FF 4096
#define VV 50257
#define TT 1023
#define SS 1024

#define GRID 148
#define QS 32
#define FS 32
#define AS 64
#define MS 128
#define TS 4
#define NCH 16
#define CH 3142   // ceil(VV/NCH)

// ---------------- scratch (static device, no allocation) ----------------
__device__ __align__(16) float g_h[BB * EE];
__device__ __align__(16) float g_x[BB * EE];
__device__ __align__(16) float g_qkv[QS * BB * 3 * EE];
__device__ __align__(16) float g_ap[BB * HH * TS * 66];
__device__ __align__(16) float g_aproj[AS * BB * EE];
__device__ __align__(16) float g_fc[FS * BB * FF];
__device__ __align__(16) float g_mp[MS * BB * EE];
__device__ __align__(16) float g_logits[BB * VV];
__device__ __align__(16) float g_pstats[BB][NCH][2];

__device__ volatile unsigned g_generation = 0;
__device__ unsigned g_arrived = 0;

// ---------------- shared-memory union (max 32KB, under 48KB static limit) ----------------
union SMem {
    struct { float4 cmb[2][4][128]; float xs[256]; } gemv;                       // ~17.4KB
    struct { float qs[64], kn[64], vn[64]; float gm[32], gd[32];
             float gacc[32][64]; } attn;                                         // ~9.2KB
    struct { float4 ps[2][256]; } resid;                                         // 8KB
    struct { float4 xs[8][256]; } logits;                                        // 32KB
};

// ---------------- grid barrier (sense-reversal, all 148 blocks resident) ----------------
__device__ __forceinline__ void grid_barrier(unsigned& gen) {
    __threadfence();
    __syncthreads();
    if (threadIdx.x == 0) {
        unsigned old = atomicAdd(&g_arrived, 1u);
        if (old == GRID - 1) {
            g_arrived = 0;
            __threadfence();
            g_generation = gen + 1;
        } else {
            unsigned ns = 8;
            while (g_generation == gen) { __nanosleep(ns); if (ns < 256) ns += ns; }
        }
        __threadfence();
    }
    __syncthreads();
    gen = gen + 1;
}

// ---------------- 512-thread block reductions ----------------
__device__ __forceinline__ float bsum512(float v, float* red) {
    #pragma unroll
    for (int o = 16; o; o >>= 1) v += __shfl_down_sync(0xffffffffu, v, o);
    int tid = threadIdx.x;
    if ((tid & 31) == 0) red[tid >> 5] = v;
    __syncthreads();
    if (tid == 0) {
        float s = red[0];
        #pragma unroll
        for (int i = 1; i < 16; i++) s += red[i];
        red[0] = s;
    }
    __syncthreads();
    float r = red[0];
    __syncthreads();
    return r;
}

__device__ __forceinline__ float bmax512(float v, float* red) {
    #pragma unroll
    for (int o = 16; o; o >>= 1) v = fmaxf(v, __shfl_down_sync(0xffffffffu, v, o));
    int tid = threadIdx.x;
    if ((tid & 31) == 0) red[tid >> 5] = v;
    __syncthreads();
    if (tid == 0) {
        float s = red[0];
        #pragma unroll
        for (int i = 1; i < 16; i++) s = fmaxf(s, red[i]);
        red[0] = s;
    }
    __syncthreads();
    float r = red[0];
    __syncthreads();
    return r;
}

// ---------------- GEMV unit: 512 thr = 128 cols x 2 ksub x 2 bsub, split-K partial ----------------
template<int KCB, int N>
__device__ __forceinline__ void gemv_unit(const float* __restrict__ W, float* part,
                                          int cb, int sp, const float* xs,
                                          float4 (*cmb)[4][128]) {
    constexpr int KH = KCB / 2;
    int tid = threadIdx.x;
    int col = tid & 127, ksub = (tid >> 7) & 1, bsub = tid >> 8;
    int n4 = cb * 128 + col;
    const float4* wp = ((const float4*)W) + (size_t)(sp * KCB + ksub * KH) * (N / 4) + n4;
    const float* xk = xs + bsub * 4 * KCB + ksub * KH;
    float4 acc[4];
    #pragma unroll
    for (int b = 0; b < 4; b++) { acc[b].x = 0.f; acc[b].y = 0.f; acc[b].z = 0.f; acc[b].w = 0.f; }
    #pragma unroll
    for (int k = 0; k < KH; k++) {
        float4 wv = wp[(size_t)k * (N / 4)];
        #pragma unroll
        for (int b = 0; b < 4; b++) {
            float xv = xk[b * KCB + k];
            acc[b].x = fmaf(xv, wv.x, acc[b].x);
            acc[b].y = fmaf(xv, wv.y, acc[b].y);
            acc[b].z = fmaf(xv, wv.z, acc[b].z);
            acc[b].w = fmaf(xv, wv.w, acc[b].w);
        }
    }
    if (ksub == 1) {
        #pragma unroll
        for (int b = 0; b < 4; b++) cmb[bsub][b][col] = acc[b];
    }
    __syncthreads();
    if (ksub == 0) {
        #pragma unroll
        for (int b = 0; b < 4; b++) {
            float4 o = cmb[bsub][b][col];
            o.x += acc[b].x; o.y += acc[b].y; o.z += acc[b].z; o.w += acc[b].w;
            ((float4*)part)[(size_t)(sp * 8 + bsub * 4 + b) * (N / 4) + n4] = o;
        }
    }
    __syncthreads();
}

// ---------------- resid+LN unit (512 threads) ----------------
__device__ __forceinline__ void resid_unit(const float4* part, int NS, int u,
                                           const float* bias, const float* lw, const float* lb,
                                           SMem* sm, float* red) {
    int tid = threadIdx.x;
    int c = tid & 255, grp = tid >> 8;
    float4 v; v.x = v.y = v.z = v.w = 0.f;
    #pragma unroll 8
    for (int sp = grp; sp < NS; sp += 2) {
        float4 p = __ldcg(&part[(size_t)(sp * 8 + u) * 256 + c]);
        v.x += p.x; v.y += p.y; v.z += p.z; v.w += p.w;
    }
    sm->resid.ps[grp][c] = v;
    __syncthreads();
    float4 hv; hv.x = hv.y = hv.z = hv.w = 0.f;
    if (grp == 0) {
        float4 h4 = __ldcg(((const float4*)g_h) + u * 256 + c);
        float4 bv = ((const float4*)bias)[c];
        float4 s1 = sm->resid.ps[1][c];
        hv.x = v.x + s1.x + h4.x + bv.x;
        hv.y = v.y + s1.y + h4.y + bv.y;
        hv.z = v.z + s1.z + h4.z + bv.z;
        hv.w = v.w + s1.w + h4.w + bv.w;
        ((float4*)g_h)[u * 256 + c] = hv;
    }
    float ls = (grp == 0) ? (hv.x + hv.y + hv.z + hv.w) : 0.f;
    float mean = bsum512(ls, red) * (1.f / EE);
    float dx = hv.x - mean, dy = hv.y - mean, dz = hv.z - mean, dw = hv.w - mean;
    ls = (grp == 0) ? (dx * dx + dy * dy + dz * dz + dw * dw) : 0.f;
    float rstd = rsqrtf(bsum512(ls, red) * (1.f / EE) + 1e-5f);
    if (grp == 0) {
        float4 w4 = ((const float4*)lw)[c];
        float4 b4 = ((const float4*)lb)[c];
        float4 o;
        o.x = dx * rstd * w4.x + b4.x;
        o.y = dy * rstd * w4.y + b4.y;
        o.z = dz * rstd * w4.z + b4.z;
        o.w = dw * rstd * w4.w + b4.w;
        ((float4*)g_x)[u * 256 + c] = o;
    }
    __syncthreads();
}

// ---------------- the persistent mega-kernel ----------------
__global__ void __launch_bounds__(512) mega_kernel(
    const int* __restrict__ ids, const float* __restrict__ kc, const float* __restrict__ vc,
    const float* __restrict__ wte, const float* __restrict__ wpe,
    const float* __restrict__ l1w, const float* __restrict__ l1b,
    const float* __restrict__ caw, const float* __restrict__ cab,
    const float* __restrict__ apw, const float* __restrict__ apb,
    const float* __restrict__ l2w, const float* __restrict__ l2b,
    const float* __restrict__ fw, const float* __restrict__ fb,
    const float* __restrict__ pw, const float* __restrict__ pb,
    const float* __restrict__ lnfw, const float* __restrict__ lnfb,
    const float* __restrict__ ab, float* __restrict__ out)
{
    __shared__ SMem sm;
    __shared__ float red[16];
    __shared__ float sm8[8], ss8[8];
    int tid = threadIdx.x, bid = blockIdx.x;
    unsigned gen = g_generation;   // stable: no bump can occur before all blocks read

    // ======== embed + ln1(layer 0) ========
    for (int u = bid; u < BB; u += GRID) {
        int id = ids[u * SS + (SS - 1)];
        float2 v = ((const float2*)(wte + (size_t)id * EE))[tid];
        float2 p = ((const float2*)(wpe + (size_t)(SS - 1) * EE))[tid];
        v.x += p.x; v.y += p.y;
        ((float2*)g_h)[u * 512 + tid] = v;
        float mean = bsum512(v.x + v.y, red) * (1.f / EE);
        float dx = v.x - mean, dy = v.y - mean;
        float rstd = rsqrtf(bsum512(dx * dx + dy * dy, red) * (1.f / EE) + 1e-5f);
        float2 w2 = ((const float2*)l1w)[tid];
        float2 b2 = ((const float2*)l1b)[tid];
        float2 o; o.x = dx * rstd * w2.x + b2.x; o.y = dy * rstd * w2.y + b2.y;
        ((float2*)g_x)[u * 512 + tid] = o;
    }
    grid_barrier(gen);

    for (int l = 0; l < LL; l++) {
        const float* cawl = caw + (size_t)l * EE * 3 * EE;
        const float* cabl = cab + (size_t)l * 3 * EE;
        const float* kcl  = kc + (size_t)l * BB * HH * TT * DD;
        const float* vcl  = vc + (size_t)l * BB * HH * TT * DD;
        float abias = ab[l];

        // ---- qkv GEMV (192 units) ----
        for (int u = bid; u < 6 * QS; u += GRID) {
            int cb = u % 6, sp = u / 6;
            if (tid < 8 * 32) {
                int b = tid >> 5, k = tid & 31;
                sm.gemv.xs[tid] = __ldcg(&g_x[b * EE + sp * 32 + k]);
            }
            __syncthreads();
            gemv_unit<32, 3 * EE>(cawl, g_qkv, cb, sp, sm.gemv.xs, sm.gemv.cmb);
        }
        grid_barrier(gen);

        // ---- attention (512 units = 128 bh x 4 ts, 256 keys each) ----
        for (int u = bid; u < BB * HH * TS; u += GRID) {
            int bh = u >> 2, ts = u & 3;
            int b = bh >> 4, h = bh & 15;
            if (tid < 192) {
                int grp = tid >> 6, d = tid & 63;
                int j = grp * EE + h * DD + d;
                float v = cabl[j];
                #pragma unroll 16
                for (int s = 0; s < QS; s++) v += __ldcg(&g_qkv[(size_t)(s * 8 + b) * 3 * EE + j]);
                if (grp == 0) sm.attn.qs[d] = v;
                else if (grp == 1) sm.attn.kn[d] = v;
                else sm.attn.vn[d] = v;
            }
            __syncthreads();
            int g = tid >> 4, sub = tid & 15;
            float4 qv = ((const float4*)sm.attn.qs)[sub];
            size_t rowbase = (size_t)(b * HH + h) * TT;
            int t0 = ts * 256;
            float4 kk[8], vv[8];
            #pragma unroll
            for (int j = 0; j < 8; j++) {
                int t = t0 + j * 32 + g;
                const float4* kr = (t < TT) ? (const float4*)(kcl + (rowbase + t) * DD)
                                            : (const float4*)sm.attn.kn;
                kk[j] = kr[sub];
            }
            #pragma unroll
            for (int j = 0; j < 8; j++) {
                int t = t0 + j * 32 + g;
                const float4* vr = (t < TT) ? (const float4*)(vcl + (rowbase + t) * DD)
                                            : (const float4*)sm.attn.vn;
                vv[j] = vr[sub];
            }
            float p[8];
            #pragma unroll
            for (int j = 0; j < 8; j++) {
                float s = kk[j].x * qv.x + kk[j].y * qv.y + kk[j].z * qv.z + kk[j].w * qv.w;
                s += __shfl_xor_sync(0xffffffffu, s, 8);
                s += __shfl_xor_sync(0xffffffffu, s, 4);
                s += __shfl_xor_sync(0xffffffffu, s, 2);
                s += __shfl_xor_sync(0xffffffffu, s, 1);
                p[j] = s * 0.125f + abias;
            }
            float m = p[0];
            #pragma unroll
            for (int j = 1; j < 8; j++) m = fmaxf(m, p[j]);
            float den = 0.f;
            float4 acc; acc.x = acc.y = acc.z = acc.w = 0.f;
            #pragma unroll
            for (int j = 0; j < 8; j++) {
                float e = __expf(p[j] - m);
                den += e;
                acc.x = fmaf(e, vv[j].x, acc.x);
                acc.y = fmaf(e, vv[j].y, acc.y);
                acc.z = fmaf(e, vv[j].z, acc.z);
                acc.w = fmaf(e, vv[j].w, acc.w);
            }
            if (sub == 0) { sm.attn.gm[g] = m; sm.attn.gd[g] = den; }
            ((float4*)sm.attn.gacc[g])[sub] = acc;
            __syncthreads();
            if (tid < DD) {
                float gm = -1e30f;
                #pragma unroll
                for (int g2 = 0; g2 < 32; g2++) gm = fmaxf(gm, sm.attn.gm[g2]);
                float dd = 0.f, val = 0.f;
                #pragma unroll
                for (int g2 = 0; g2 < 32; g2++) {
                    float e = __expf(sm.attn.gm[g2] - gm);
                    dd += sm.attn.gd[g2] * e;
                    val += sm.attn.gacc[g2][tid] * e;
                }
                float* app = &g_ap[((size_t)bh * TS + ts) * 66];
                if (tid == 0) { app[0] = gm; app[1] = dd; }
                app[2 + tid] = val;
            }
            __syncthreads();
        }
        grid_barrier(gen);

        // ---- attn proj GEMV (128 units, combine fused) ----
        {
            const float* apwl = apw + (size_t)l * EE * EE;
            for (int u = bid; u < 2 * AS; u += GRID) {
                int cb = u & 1, sp = u >> 1;
                if (tid < 8 * 16) {
                    int b = tid >> 4;
                    int kg = sp * 16 + (tid & 15);
                    int head = kg >> 6, d = kg & 63;
                    const float* app = &g_ap[(size_t)(b * HH + head) * TS * 66];
                    float gm = -1e30f;
                    #pragma unroll
                    for (int ts = 0; ts < TS; ts++) gm = fmaxf(gm, __ldcg(&app[ts * 66]));
                    float den = 0.f, val = 0.f;
                    #pragma unroll
                    for (int ts = 0; ts < TS; ts++) {
                        float e = __expf(__ldcg(&app[ts * 66]) - gm);
                        den += __ldcg(&app[ts * 66 + 1]) * e;
                        val += __ldcg(&app[ts * 66 + 2 + d]) * e;
                    }
                    sm.gemv.xs[tid] = val / den;
                }
                __syncthreads();
                gemv_unit<16, EE>(apwl, g_aproj, cb, sp, sm.gemv.xs, sm.gemv.cmb);
            }
        }
        grid_barrier(gen);

        // ---- resid1 + ln2 (8 units) ----
        for (int u = bid; u < BB; u += GRID)
            resid_unit((const float4*)g_aproj, AS, u, apb + (size_t)l * EE,
                       l2w + (size_t)l * EE, l2b + (size_t)l * EE, &sm, red);
        grid_barrier(gen);

        // ---- fc GEMV (256 units) ----
        {
            const float* fwl = fw + (size_t)l * EE * FF;
            for (int u = bid; u < 8 * FS; u += GRID) {
                int cb = u % 8, sp = u / 8;
                if (tid < 8 * 32) {
                    int b = tid >> 5, k = tid & 31;
                    sm.gemv.xs[tid] = __ldcg(&g_x[b * EE + sp * 32 + k]);
                }
                __syncthreads();
                gemv_unit<32, FF>(fwl, g_fc, cb, sp, sm.gemv.xs, sm.gemv.cmb);
            }
        }
        grid_barrier(gen);

        // ---- mlp proj GEMV with fused gelu input (256 units) ----
        {
            const float* pwl = pw + (size_t)l * FF * EE;
            const float* fbl = fb + (size_t)l * FF;
            for (int u = bid; u < 2 * MS; u += GRID) {
                int cb = u & 1, sp = u >> 1;
                if (tid < 8 * 32) {
                    int b = tid >> 5, k = sp * 32 + (tid & 31);
                    float v = fbl[k];
                    #pragma unroll 16
                    for (int s = 0; s < FS; s++) v += __ldcg(&g_fc[(size_t)(s * 8 + b) * FF + k]);
                    float c3 = v * v * v;
                    sm.gemv.xs[tid] = 0.5f * v * (1.f + tanhf(0.7978845608028654f * (v + 0.044715f * c3)));
                }
                __syncthreads();
                gemv_unit<32, EE>(pwl, g_mp, cb, sp, sm.gemv.xs, sm.gemv.cmb);
            }
        }
        grid_barrier(gen);

        // ---- resid2 + ln1(next) / lnf (8 units) ----
        {
            const float* nlw = (l < LL - 1) ? (l1w + (size_t)(l + 1) * EE) : lnfw;
            const float* nlb = (l < LL - 1) ? (l1b + (size_t)(l + 1) * EE) : lnfb;
            for (int u = bid; u < BB; u += GRID)
                resid_unit((const float4*)g_mp, MS, u, pb + (size_t)l * EE, nlw, nlb, &sm, red);
        }
        grid_barrier(gen);
    }

    // ======== logits: 4 rows x 4 batches per warp ========
    for (int i = tid; i < 2048; i += 512) {
        int b = i >> 8, j = i & 255;
        sm.logits.xs[b][j] = __ldcg(((const float4*)g_x) + b * 256 + j);
    }
    __syncthreads();
    {
        int w = tid >> 5, lane = tid & 31;
        int bsub = w >> 3, w8 = w & 7;
        for (int u = bid; u < 1571; u += GRID) {
            int v0 = (u * 8 + w8) * 4;
            if (v0 >= VV) continue;
            const float4* r0 = (const float4*)(wte + (size_t)v0 * EE);
            const float4* r1 = (const float4*)(wte + (size_t)((v0 + 1 < VV) ? v0 + 1 : v0) * EE);
            const float4* r2 = (const float4*)(wte + (size_t)((v0 + 2 < VV) ? v0 + 2 : v0) * EE);
            const float4* r3 = (const float4*)(wte + (size_t)((v0 + 3 < VV) ? v0 + 3 : v0) * EE);
            float a0[4], a1[4], a2[4], a3[4];
            #pragma unroll
            for (int b = 0; b < 4; b++) { a0[b] = a1[b] = a2[b] = a3[b] = 0.f; }
            #pragma unroll
            for (int i2 = 0; i2 < 8; i2++) {
                int idx = lane + 32 * i2;
                float4 w0 = r0[idx], w1 = r1[idx], w2 = r2[idx], w3 = r3[idx];
                #pragma unroll
                for (int b = 0; b < 4; b++) {
                    float4 xb = sm.logits.xs[bsub * 4 + b][idx];
                    a0[b] += w0.x * xb.x + w0.y * xb.y + w0.z * xb.z + w0.w * xb.w;
                    a1[b] += w1.x * xb.x + w1.y * xb.y + w1.z * xb.z + w1.w * xb.w;
                    a2[b] += w2.x * xb.x + w2.y * xb.y + w2.z * xb.z + w2.w * xb.w;
                    a3[b] += w3.x * xb.x + w3.y * xb.y + w3.z * xb.z + w3.w * xb.w;
                }
            }
            #pragma unroll
            for (int b = 0; b < 4; b++) {
                #pragma unroll
                for (int o = 16; o; o >>= 1) {
                    a0[b] += __shfl_down_sync(0xffffffffu, a0[b], o);
                    a1[b] += __shfl_down_sync(0xffffffffu, a1[b], o);
                    a2[b] += __shfl_down_sync(0xffffffffu, a2[b], o);
                    a3[b] += __shfl_down_sync(0xffffffffu, a3[b], o);
                }
            }
            if (lane == 0) {
                #pragma unroll
                for (int b = 0; b < 4; b++) {
                    int bb = bsub * 4 + b;
                    g_logits[(size_t)bb * VV + v0] = a0[b];
                    if (v0 + 1 < VV) g_logits[(size_t)bb * VV + v0 + 1] = a1[b];
                    if (v0 + 2 < VV) g_logits[(size_t)bb * VV + v0 + 2] = a2[b];
                    if (v0 + 3 < VV) g_logits[(size_t)bb * VV + v0 + 3] = a3[b];
                }
            }
        }
    }
    grid_barrier(gen);

    // ======== softmax partial stats (128 units) ========
    for (int u = bid; u < BB * NCH; u += GRID) {
        int b = u >> 4, ch = u & 15;
        int start = ch * CH;
        int end = (start + CH < VV) ? start + CH : VV;
        const float* lg = g_logits + (size_t)b * VV;
        float m = -1e30f;
        for (int v = start + tid; v < end; v += 512) m = fmaxf(m, __ldcg(&lg[v]));
        m = bmax512(m, red);
        float s = 0.f;
        for (int v = start + tid; v < end; v += 512) s += __expf(__ldcg(&lg[v]) - m);
        s = bsum512(s, red);
        if (tid == 0) { g_pstats[b][ch][0] = m; g_pstats[b][ch][1] = s; }
    }
    grid_barrier(gen);

    // ======== softmax normalize ========
    if (tid < 8) {
        float m = -1e30f;
        #pragma unroll
        for (int c = 0; c < NCH; c++) m = fmaxf(m, __ldcg(&g_pstats[tid][c][0]));
        float s = 0.f;
        #pragma unroll
        for (int c = 0; c < NCH; c++)
            s += __ldcg(&g_pstats[tid][c][1]) * __expf(__ldcg(&g_pstats[tid][c][0]) - m);
        sm8[tid] = m; ss8[tid] = 1.f / s;
    }
    __syncthreads();
    for (int i = bid * 512 + tid; i < BB * VV; i += GRID * 512) {
        int b = i / VV;
        out[i] = __expf(__ldcg(&g_logits[i]) - sm8[b]) * ss8[b];
    }
}

// ---------------- launch: ONE persistent kernel ----------------
extern "C" void kernel_launch(void* const* d_in, const int* in_sizes, int n_in,
                              void* d_out, int out_size) {
    const int*   ids  = (const int*)  d_in[0];
    const float* kc   = (const float*)d_in[1];
    const float* vc   = (const float*)d_in[2];
    const float* wte  = (const float*)d_in[3];
    const float* wpe  = (const float*)d_in[4];
    const float* l1w  = (const float*)d_in[5];
    const float* l1b  = (const float*)d_in[6];
    const float* caw  = (const float*)d_in[7];
    const float* cab  = (const float*)d_in[8];
    const float* apw  = (const float*)d_in[9];
    const float* apb  = (const float*)d_in[10];
    const float* l2w  = (const float*)d_in[11];
    const float* l2b  = (const float*)d_in[12];
    const float* fw   = (const float*)d_in[13];
    const float* fb   = (const float*)d_in[14];
    const float* pw   = (const float*)d_in[15];
    const float* pb   = (const float*)d_in[16];
    const float* lnfw = (const float*)d_in[17];
    const float* lnfb = (const float*)d_in[18];
    const float* ab   = (const float*)d_in[19];
    float* out = (float*)d_out;

    mega_kernel<<<GRID, 512>>>(ids, kc, vc, wte, wpe, l1w, l1b, caw, cab,
                               apw, apb, l2w, l2b, fw, fb, pw, pb,
                               lnfw, lnfb, ab, out);
}

// round 15
// speedup vs baseline: 1.1675x; 1.1675x over previous
#include <cuda_runtime.h>
#include <cuda_bf16.h>
#include <math.h>

// Problem constants
#define LL 12
#define BB 8
#define HH 16
#define DD 64
#define EE 1024
#define FF 4096
#define VV 50257
#define TT 1023
#define SS 1024

// Split configs
#define QS 32    // qkv K-splits (KCB=32)
#define FS 32    // fc K-splits (KCB=32)
#define AS 64    // attnproj K-splits (KCB=16)
#define MS 64    // mlpproj K-splits (KCB=64)
#define TS 8     // attention T splits (1024/128)
#define NCH 32   // softmax stats chunks per batch

// ---------------- scratch (static device, no allocation) ----------------
__device__ __align__(16) float g_h[BB * EE];
__device__ __align__(16) float g_x[BB * EE];
__device__ __align__(16) float g_qkv[QS * BB * 3 * EE];
__device__ __align__(16) float g_ap[BB * HH * TS * 66];   // [bh][ts][m,den,64 vals]
__device__ __align__(16) float g_aproj[AS * BB * EE];
__device__ __align__(16) float g_fc[FS * BB * FF];
__device__ __align__(16) float g_mp[MS * BB * EE];
__device__ __align__(16) float g_logits[BB * VV];
__device__ __align__(16) float g_pstats[BB][NCH][2];

// Scratch selection in DEVICE code only (host-side __device__ symbol = bogus addr).
#define BUF_QKV   0
#define BUF_APROJ 1
#define BUF_FC    2
#define BUF_MP    3
template<int ID>
__device__ __forceinline__ float* scratch_buf() {
    if (ID == BUF_QKV)   return g_qkv;
    if (ID == BUF_APROJ) return g_aproj;
    if (ID == BUF_FC)    return g_fc;
    return g_mp;
}

// ---------------- reductions ----------------
__device__ __forceinline__ float blockReduceSum256(float v, float* red) {
    #pragma unroll
    for (int o = 16; o; o >>= 1) v += __shfl_down_sync(0xffffffffu, v, o);
    int tid = threadIdx.x;
    if ((tid & 31) == 0) red[tid >> 5] = v;
    __syncthreads();
    if (tid == 0) {
        float s = red[0];
        #pragma unroll
        for (int i = 1; i < 8; i++) s += red[i];
        red[0] = s;
    }
    __syncthreads();
    float r = red[0];
    __syncthreads();
    return r;
}

__device__ __forceinline__ float blockReduceMax256(float v, float* red) {
    #pragma unroll
    for (int o = 16; o; o >>= 1) v = fmaxf(v, __shfl_down_sync(0xffffffffu, v, o));
    int tid = threadIdx.x;
    if ((tid & 31) == 0) red[tid >> 5] = v;
    __syncthreads();
    if (tid == 0) {
        float s = red[0];
        #pragma unroll
        for (int i = 1; i < 8; i++) s = fmaxf(s, red[i]);
        red[0] = s;
    }
    __syncthreads();
    float r = red[0];
    __syncthreads();
    return r;
}

__device__ __forceinline__ float blockReduceSum1024(float v, float* red) {
    #pragma unroll
    for (int o = 16; o; o >>= 1) v += __shfl_down_sync(0xffffffffu, v, o);
    int tid = threadIdx.x;
    if ((tid & 31) == 0) red[tid >> 5] = v;
    __syncthreads();
    if (tid == 0) {
        float s = red[0];
        #pragma unroll
        for (int i = 1; i < 32; i++) s += red[i];
        red[0] = s;
    }
    __syncthreads();
    float r = red[0];
    __syncthreads();
    return r;
}

// ---------------- embed + ln1(layer 0) ----------------
__global__ void embed_kernel(const int* __restrict__ ids,
                             const float* __restrict__ wte,
                             const float* __restrict__ wpe,
                             const float* __restrict__ lw,
                             const float* __restrict__ lb) {
    __shared__ float red[8];
    int b = blockIdx.x, tid = threadIdx.x;   // 256 threads, one float4 each
    int id = ids[b * SS + (SS - 1)];
    float4 v = ((const float4*)(wte + (size_t)id * EE))[tid];
    float4 p = ((const float4*)(wpe + (size_t)(SS - 1) * EE))[tid];
    v.x += p.x; v.y += p.y; v.z += p.z; v.w += p.w;
    ((float4*)g_h)[b * 256 + tid] = v;
    float ls = v.x + v.y + v.z + v.w;
    float mean = blockReduceSum256(ls, red) * (1.f / EE);
    float dx = v.x - mean, dy = v.y - mean, dz = v.z - mean, dw = v.w - mean;
    ls = dx * dx + dy * dy + dz * dz + dw * dw;
    float rstd = rsqrtf(blockReduceSum256(ls, red) * (1.f / EE) + 1e-5f);
    float4 w4 = ((const float4*)lw)[tid];
    float4 b4 = ((const float4*)lb)[tid];
    float4 o;
    o.x = dx * rstd * w4.x + b4.x;
    o.y = dy * rstd * w4.y + b4.y;
    o.z = dz * rstd * w4.z + b4.z;
    o.w = dw * rstd * w4.w + b4.w;
    ((float4*)g_x)[b * 256 + tid] = o;
}

// ---------------- GEMV core: software-pipelined, 256 thr = 128 cols x 2 bsub ----------------
// PF=8 rolling buffer of weight float4 loads keeps 8 LDG.128 in flight per thread.
// 4-batch accumulators (16 regs) leave room for the 32-reg staging buffer.
template<int KCB, int N>
__device__ __forceinline__ void gemv_core4(const float* xs,
                                           const float* __restrict__ W,
                                           float* __restrict__ part) {
    constexpr int PF = (KCB < 8) ? KCB : 8;
    int tid = threadIdx.x;
    int col = tid & 127, bsub = tid >> 7;          // bsub: batches 0-3 / 4-7
    int n4 = blockIdx.x * 128 + col;               // float4 column index
    int sp = blockIdx.y;
    const float4* wp = ((const float4*)W) + (size_t)(sp * KCB) * (N / 4) + n4;
    const float* xk = xs + bsub * 4 * KCB;
    float4 acc[4];
    #pragma unroll
    for (int b = 0; b < 4; b++) { acc[b].x = 0.f; acc[b].y = 0.f; acc[b].z = 0.f; acc[b].w = 0.f; }
    float4 buf[PF];
    #pragma unroll
    for (int i = 0; i < PF; i++) buf[i] = wp[(size_t)i * (N / 4)];
    #pragma unroll
    for (int k = 0; k < KCB; k++) {
        float4 wv = buf[k % PF];
        if (k + PF < KCB) buf[k % PF] = wp[(size_t)(k + PF) * (N / 4)];
        #pragma unroll
        for (int b = 0; b < 4; b++) {
            float xv = xk[b * KCB + k];
            acc[b].x = fmaf(xv, wv.x, acc[b].x);
            acc[b].y = fmaf(xv, wv.y, acc[b].y);
            acc[b].z = fmaf(xv, wv.z, acc[b].z);
            acc[b].w = fmaf(xv, wv.w, acc[b].w);
        }
    }
    float4* p4 = (float4*)part;
    #pragma unroll
    for (int b = 0; b < 4; b++)
        p4[(size_t)(sp * 8 + bsub * 4 + b) * (N / 4) + n4] = acc[b];
}

// plain: input = g_x, output = scratch_buf<DST>
template<int KCB, int N, int K, int DST>
__global__ void __launch_bounds__(256) gemv_k(const float* __restrict__ W) {
    __shared__ float xs[8 * KCB];
    int tid = threadIdx.x;
    int k0 = blockIdx.y * KCB;
    for (int i = tid; i < 8 * KCB; i += 256) {
        int b = i / KCB, k = i % KCB;
        xs[i] = g_x[b * K + k0 + k];
    }
    __syncthreads();
    gemv_core4<KCB, N>(xs, W, scratch_buf<DST>());
}

// gelu: input = sum of fc partials + bias, gelu'd  (K = FF)
template<int KCB, int N, int DST>
__global__ void __launch_bounds__(256) gemv_gelu_k(const float* __restrict__ fcb,
                                                   const float* __restrict__ W) {
    __shared__ float xs[8 * KCB];
    int tid = threadIdx.x;
    int k0 = blockIdx.y * KCB;
    for (int i = tid; i < 8 * KCB; i += 256) {
        int b = i / KCB, k = k0 + i % KCB;
        float v = fcb[k];
        #pragma unroll 16
        for (int s = 0; s < FS; s++) v += g_fc[(size_t)(s * 8 + b) * FF + k];
        float c3 = v * v * v;
        xs[i] = 0.5f * v * (1.f + tanhf(0.7978845608028654f * (v + 0.044715f * c3)));
    }
    __syncthreads();
    gemv_core4<KCB, N>(xs, W, scratch_buf<DST>());
}

// ctx: input built from attention partials (flash-decode combine), K = EE
template<int KCB, int N, int DST>
__global__ void __launch_bounds__(256) gemv_ctx_k(const float* __restrict__ W) {
    __shared__ float xs[8 * KCB];
    int tid = threadIdx.x;
    int k0 = blockIdx.y * KCB;
    if (tid < 8 * KCB) {
        int b = tid / KCB;
        int kg = k0 + tid % KCB;
        int head = kg >> 6, d = kg & 63;
        int bh = b * HH + head;
        const float* ap = &g_ap[(size_t)bh * TS * 66];
        float gm = -1e30f;
        #pragma unroll
        for (int ts = 0; ts < TS; ts++) gm = fmaxf(gm, ap[ts * 66]);
        float den = 0.f, val = 0.f;
        #pragma unroll
        for (int ts = 0; ts < TS; ts++) {
            float e = __expf(ap[ts * 66] - gm);
            den += ap[ts * 66 + 1] * e;
            val += ap[ts * 66 + 2 + d] * e;
        }
        xs[tid] = val / den;
    }
    __syncthreads();
    gemv_core4<KCB, N>(xs, W, scratch_buf<DST>());
}

// ---------------- attention: fused qkv combine + register-resident two-pass ----------------
__global__ void __launch_bounds__(256, 2) attn_kernel(const float* __restrict__ kc,
                                                      const float* __restrict__ vc,
                                                      const float* __restrict__ cab,
                                                      const float* __restrict__ abp) {
    __shared__ __align__(16) float qs[DD], kn[DD], vn[DD];
    __shared__ float gm_s[16], gd_s[16];
    __shared__ __align__(16) float gacc[16][DD];
    int tid = threadIdx.x;
    int bh = blockIdx.x;
    int b = bh >> 4, h = bh & 15;
    int ts = blockIdx.y;

    // fused qkv split-combine for this (b, head): 192 values (q, k_new, v_new)
    if (tid < 192) {
        int grp = tid >> 6;         // 0:q 1:k 2:v
        int d = tid & 63;
        int j = grp * EE + h * DD + d;
        float v = cab[j];
        #pragma unroll 16
        for (int s = 0; s < QS; s++) v += g_qkv[(size_t)(s * 8 + b) * (3 * EE) + j];
        if (grp == 0) qs[d] = v; else if (grp == 1) kn[d] = v; else vn[d] = v;
    }
    __syncthreads();

    int w = tid >> 5, lane = tid & 31;
    int half = lane >> 4, sub = lane & 15;
    int g = w * 2 + half;                 // 16 lane-groups of 16
    float4 qv = ((const float4*)qs)[sub];
    const float4* knp = (const float4*)kn;
    const float4* vnp = (const float4*)vn;
    size_t rowbase = (size_t)(b * HH + h) * TT;
    int t0 = ts * 128;
    float abias = abp[0];

    // issue all 16 independent LDG.128 before any math
    float4 kk[8], vv[8];
    #pragma unroll
    for (int j = 0; j < 8; j++) {
        int t = t0 + j * 16 + g;
        const float4* kr = (t < TT) ? (const float4*)(kc + (rowbase + t) * DD) : knp;
        kk[j] = kr[sub];
    }
    #pragma unroll
    for (int j = 0; j < 8; j++) {
        int t = t0 + j * 16 + g;
        const float4* vr = (t < TT) ? (const float4*)(vc + (rowbase + t) * DD) : vnp;
        vv[j] = vr[sub];
    }

    float p[8];
    #pragma unroll
    for (int j = 0; j < 8; j++) {
        float s = kk[j].x * qv.x + kk[j].y * qv.y + kk[j].z * qv.z + kk[j].w * qv.w;
        s += __shfl_xor_sync(0xffffffffu, s, 8);
        s += __shfl_xor_sync(0xffffffffu, s, 4);
        s += __shfl_xor_sync(0xffffffffu, s, 2);
        s += __shfl_xor_sync(0xffffffffu, s, 1);
        p[j] = s * 0.125f + abias;
    }
    float m = p[0];
    #pragma unroll
    for (int j = 1; j < 8; j++) m = fmaxf(m, p[j]);
    float den = 0.f;
    float4 acc; acc.x = acc.y = acc.z = acc.w = 0.f;
    #pragma unroll
    for (int j = 0; j < 8; j++) {
        float e = __expf(p[j] - m);
        den += e;
        acc.x = fmaf(e, vv[j].x, acc.x);
        acc.y = fmaf(e, vv[j].y, acc.y);
        acc.z = fmaf(e, vv[j].z, acc.z);
        acc.w = fmaf(e, vv[j].w, acc.w);
    }

    if (sub == 0) { gm_s[g] = m; gd_s[g] = den; }
    ((float4*)gacc[g])[sub] = acc;
    __syncthreads();

    if (tid < DD) {
        float gm = -1e30f;
        #pragma unroll
        for (int g2 = 0; g2 < 16; g2++) gm = fmaxf(gm, gm_s[g2]);
        float dd = 0.f, val = 0.f;
        #pragma unroll
        for (int g2 = 0; g2 < 16; g2++) {
            float e = __expf(gm_s[g2] - gm);
            dd += gd_s[g2] * e;
            val += gacc[g2][tid] * e;
        }
        float* ap = &g_ap[((size_t)bh * TS + ts) * 66];
        if (tid == 0) { ap[0] = gm; ap[1] = dd; }
        ap[2 + tid] = val;
    }
}

// ---------------- residual (sum split partials + bias) + layernorm -> g_x ----------------
template<int SRC, int NS>
__global__ void __launch_bounds__(1024) resid_ln_kernel(const float* __restrict__ bias,
                                                        const float* __restrict__ lw,
                                                        const float* __restrict__ lb) {
    __shared__ __align__(16) float4 ps[4][256];
    __shared__ float red[32];
    const float4* part = (const float4*)scratch_buf<SRC>();
    int b = blockIdx.x, tid = threadIdx.x;
    int c = tid & 255, grp = tid >> 8;
    float4 v; v.x = v.y = v.z = v.w = 0.f;
    #pragma unroll 16
    for (int sp = grp; sp < NS; sp += 4) {
        float4 p = part[(size_t)(sp * 8 + b) * 256 + c];
        v.x += p.x; v.y += p.y; v.z += p.z; v.w += p.w;
    }
    ps[grp][c] = v;
    __syncthreads();
    float4 hv; hv.x = hv.y = hv.z = hv.w = 0.f;
    if (grp == 0) {
        float4 h4 = ((const float4*)g_h)[b * 256 + c];
        float4 bv = ((const float4*)bias)[c];
        float4 s1 = ps[1][c], s2 = ps[2][c], s3 = ps[3][c];
        hv.x = v.x + s1.x + s2.x + s3.x + h4.x + bv.x;
        hv.y = v.y + s1.y + s2.y + s3.y + h4.y + bv.y;
        hv.z = v.z + s1.z + s2.z + s3.z + h4.z + bv.z;
        hv.w = v.w + s1.w + s2.w + s3.w + h4.w + bv.w;
        ((float4*)g_h)[b * 256 + c] = hv;
    }
    float ls = (grp == 0) ? (hv.x + hv.y + hv.z + hv.w) : 0.f;
    float mean = blockReduceSum1024(ls, red) * (1.f / EE);
    float dx = hv.x - mean, dy = hv.y - mean, dz = hv.z - mean, dw = hv.w - mean;
    ls = (grp == 0) ? (dx * dx + dy * dy + dz * dz + dw * dw) : 0.f;
    float rstd = rsqrtf(blockReduceSum1024(ls, red) * (1.f / EE) + 1e-5f);
    if (grp == 0) {
        float4 w4 = ((const float4*)lw)[c];
        float4 b4 = ((const float4*)lb)[c];
        float4 o;
        o.x = dx * rstd * w4.x + b4.x;
        o.y = dy * rstd * w4.y + b4.y;
        o.z = dz * rstd * w4.z + b4.z;
        o.w = dw * rstd * w4.w + b4.w;
        ((float4*)g_x)[b * 256 + c] = o;
    }
}

// ---------------- logits: 4 vocab rows per warp (one quad each), 8-batch reuse ----------------
__global__ void __launch_bounds__(256) logits_kernel(const float* __restrict__ wte) {
    __shared__ __align__(16) float4 xs[8][256];
    int tid = threadIdx.x;
    for (int i = tid; i < 2048; i += 256) {
        int b = i >> 8, j = i & 255;
        xs[b][j] = ((const float4*)g_x)[b * 256 + j];
    }
    __syncthreads();
    int gw = blockIdx.x * 8 + (tid >> 5);
    int lane = tid & 31;
    int v0 = gw * 4;
    if (v0 >= VV) return;
    const float4* r0 = (const float4*)(wte + (size_t)v0 * EE);
    const float4* r1 = (const float4*)(wte + (size_t)((v0 + 1 < VV) ? v0 + 1 : v0) * EE);
    const float4* r2 = (const float4*)(wte + (size_t)((v0 + 2 < VV) ? v0 + 2 : v0) * EE);
    const float4* r3 = (const float4*)(wte + (size_t)((v0 + 3 < VV) ? v0 + 3 : v0) * EE);
    float a0[8], a1[8], a2[8], a3[8];
    #pragma unroll
    for (int b = 0; b < 8; b++) { a0[b] = a1[b] = a2[b] = a3[b] = 0.f; }
    #pragma unroll
    for (int i = 0; i < 8; i++) {
        int idx = lane + 32 * i;
        float4 w0 = r0[idx], w1 = r1[idx], w2 = r2[idx], w3 = r3[idx];
        #pragma unroll
        for (int b = 0; b < 8; b++) {
            float4 xb = xs[b][idx];
            a0[b] += w0.x * xb.x + w0.y * xb.y + w0.z * xb.z + w0.w * xb.w;
            a1[b] += w1.x * xb.x + w1.y * xb.y + w1.z * xb.z + w1.w * xb.w;
            a2[b] += w2.x * xb.x + w2.y * xb.y + w2.z * xb.z + w2.w * xb.w;
            a3[b] += w3.x * xb.x + w3.y * xb.y + w3.z * xb.z + w3.w * xb.w;
        }
    }
    #pragma unroll
    for (int b = 0; b < 8; b++) {
        #pragma unroll
        for (int o = 16; o; o >>= 1) {
            a0[b] += __shfl_down_sync(0xffffffffu, a0[b], o);
            a1[b] += __shfl_down_sync(0xffffffffu, a1[b], o);
            a2[b] += __shfl_down_sync(0xffffffffu, a2[b], o);
            a3[b] += __shfl_down_sync(0xffffffffu, a3[b], o);
        }
    }
    if (lane == 0) {
        #pragma unroll
        for (int b = 0; b < 8; b++) {
            g_logits[(size_t)b * VV + v0] = a0[b];
            if (v0 + 1 < VV) g_logits[(size_t)b * VV + v0 + 1] = a1[b];
            if (v0 + 2 < VV) g_logits[(size_t)b * VV + v0 + 2] = a2[b];
            if (v0 + 3 < VV) g_logits[(size_t)b * VV + v0 + 3] = a3[b];
        }
    }
}

// ---------------- softmax: partial stats over 32 chunks/batch, combined in norm ----------------
#define CH ((VV + NCH - 1) / NCH)   // 1571
__global__ void __launch_bounds__(256) softmax_pstats_kernel() {
    __shared__ float red[8];
    int b = blockIdx.x, ch = blockIdx.y, tid = threadIdx.x;
    int start = ch * CH;
    int end = (start + CH < VV) ? start + CH : VV;
    const float* lg = g_logits + (size_t)b * VV;
    float m = -1e30f;
    #pragma unroll 4
    for (int v = start + tid; v < end; v += 256) m = fmaxf(m, lg[v]);
    m = blockReduceMax256(m, red);
    float s = 0.f;
    #pragma unroll 4
    for (int v = start + tid; v < end; v += 256) s += __expf(lg[v] - m);
    s = blockReduceSum256(s, red);
    if (tid == 0) { g_pstats[b][ch][0] = m; g_pstats[b][ch][1] = s; }
}

__global__ void __launch_bounds__(256) softmax_norm_kernel(float* __restrict__ out) {
    __shared__ float sm, ss;
    int i = blockIdx.x * 256 + threadIdx.x;
    int b = (blockIdx.x * 256) / VV;
    if (threadIdx.x < 32) {
        float m = g_pstats[b][threadIdx.x][0];
        #pragma unroll
        for (int o = 16; o; o >>= 1) m = fmaxf(m, __shfl_xor_sync(0xffffffffu, m, o));
        float s = g_pstats[b][threadIdx.x][1] * __expf(g_pstats[b][threadIdx.x][0] - m);
        #pragma unroll
        for (int o = 16; o; o >>= 1) s += __shfl_xor_sync(0xffffffffu, s, o);
        if (threadIdx.x == 0) { sm = m; ss = s; }
    }
    __syncthreads();
    if (i < BB * VV) {
        int be = i / VV;
        float m, s;
        if (be == b) { m = sm; s = ss; }
        else {
            m = -1e30f;
            #pragma unroll
            for (int c = 0; c < NCH; c++) m = fmaxf(m, g_pstats[be][c][0]);
            s = 0.f;
            #pragma unroll
            for (int c = 0; c < NCH; c++) s += g_pstats[be][c][1] * __expf(g_pstats[be][c][0] - m);
        }
        out[i] = __expf(g_logits[i] - m) * (1.f / s);
    }
}

// ---------------- launch ----------------
extern "C" void kernel_launch(void* const* d_in, const int* in_sizes, int n_in,
                              void* d_out, int out_size) {
    const int*   ids  = (const int*)  d_in[0];
    const float* kc   = (const float*)d_in[1];
    const float* vc   = (const float*)d_in[2];
    const float* wte  = (const float*)d_in[3];
    const float* wpe  = (const float*)d_in[4];
    const float* l1w  = (const float*)d_in[5];
    const float* l1b  = (const float*)d_in[6];
    const float* caw  = (const float*)d_in[7];
    const float* cab  = (const float*)d_in[8];
    const float* apw  = (const float*)d_in[9];
    const float* apb  = (const float*)d_in[10];
    const float* l2w  = (const float*)d_in[11];
    const float* l2b  = (const float*)d_in[12];
    const float* fw   = (const float*)d_in[13];
    const float* fb   = (const float*)d_in[14];
    const float* pw   = (const float*)d_in[15];
    const float* pb   = (const float*)d_in[16];
    const float* lnfw = (const float*)d_in[17];
    const float* lnfb = (const float*)d_in[18];
    const float* ab   = (const float*)d_in[19];
    float* out = (float*)d_out;

    embed_kernel<<<BB, 256>>>(ids, wte, wpe, l1w, l1b);

    for (int l = 0; l < LL; l++) {
        // qkv = x @ c_attn_w  (N=3072: 6 col-blocks x 32 splits) -> 192 blocks
        gemv_k<32, 3 * EE, EE, BUF_QKV><<<dim3(6, QS), 256>>>(caw + (size_t)l * EE * 3 * EE);

        // attention (fused qkv combine): 1024 blocks
        attn_kernel<<<dim3(BB * HH, TS), 256>>>(
            kc + (size_t)l * BB * HH * TT * DD,
            vc + (size_t)l * BB * HH * TT * DD,
            cab + (size_t)l * 3 * EE,
            ab + l);

        // attn proj (combine fused): N=1024: 2 col-blocks x 64 splits -> 128 blocks
        gemv_ctx_k<16, EE, BUF_APROJ><<<dim3(2, AS), 256>>>(apw + (size_t)l * EE * EE);

        // h += attnout + apb ; x = ln2(h)
        resid_ln_kernel<BUF_APROJ, AS><<<BB, 1024>>>(apb + (size_t)l * EE,
                                                     l2w + (size_t)l * EE,
                                                     l2b + (size_t)l * EE);

        // fc = x @ fc_w  (N=4096: 8 col-blocks x 32 splits) -> 256 blocks
        gemv_k<32, FF, EE, BUF_FC><<<dim3(8, FS), 256>>>(fw + (size_t)l * EE * FF);

        // mlp proj = gelu(fc + fb) @ pw  (N=1024: 2 col-blocks x 64 splits, KCB=64) -> 128 blocks
        gemv_gelu_k<64, EE, BUF_MP><<<dim3(2, MS), 256>>>(fb + (size_t)l * FF,
                                                          pw + (size_t)l * FF * EE);

        // h += mlpout + pb ; x = ln1(h,l+1)  (or lnf at the last layer)
        const float* nlw = (l < LL - 1) ? (l1w + (size_t)(l + 1) * EE) : lnfw;
        const float* nlb = (l < LL - 1) ? (l1b + (size_t)(l + 1) * EE) : lnfb;
        resid_ln_kernel<BUF_MP, MS><<<BB, 1024>>>(pb + (size_t)l * EE, nlw, nlb);
    }

    logits_kernel<<<1571, 256>>>(wte);
    softmax_pstats_kernel<<<dim3(BB, NCH), 256>>>();
    softmax_norm_kernel<<<(BB * VV + 255) / 256, 256>>>(out);
}

// round 16
// speedup vs baseline: 1.4078x; 1.2058x over previous
#include <cuda_runtime.h>
#include <cuda_bf16.h>
#include <math.h>

// Problem constants
#define LL 12
#define BB 8
#define HH 16
#define DD 64
#define EE 1024
#define FF 4096
#define VV 50257
#define TT 1023
#define SS 1024

// Split configs
#define QS 32    // qkv K-splits (KCB=32)
#define FS 32    // fc K-splits (KCB=32)
#define AS 64    // attnproj K-splits (KCB=16)
#define MS 128   // mlpproj K-splits (KCB=32)
#define TS 8     // attention T splits (1024/128)
#define NCH 32   // softmax stats chunks per batch

// ---------------- scratch (static device, no allocation) ----------------
__device__ __align__(16) float g_h[BB * EE];
__device__ __align__(16) float g_x[BB * EE];
__device__ __align__(16) float g_qkv[QS * BB * 3 * EE];
__device__ __align__(16) float g_ap[BB * HH * TS * 66];   // [bh][ts][m,den,64 vals]
__device__ __align__(16) float g_aproj[AS * BB * EE];
__device__ __align__(16) float g_fc[FS * BB * FF];
__device__ __align__(16) float g_mp[MS * BB * EE];
__device__ __align__(16) float g_logits[BB * VV];
__device__ __align__(16) float g_pstats[BB][NCH][2];

// Scratch selection in DEVICE code only (host-side __device__ symbol = bogus addr).
#define BUF_QKV   0
#define BUF_APROJ 1
#define BUF_FC    2
#define BUF_MP    3
template<int ID>
__device__ __forceinline__ float* scratch_buf() {
    if (ID == BUF_QKV)   return g_qkv;
    if (ID == BUF_APROJ) return g_aproj;
    if (ID == BUF_FC)    return g_fc;
    return g_mp;
}

// ---------------- reductions ----------------
__device__ __forceinline__ float blockReduceSum256(float v, float* red) {
    #pragma unroll
    for (int o = 16; o; o >>= 1) v += __shfl_down_sync(0xffffffffu, v, o);
    int tid = threadIdx.x;
    if ((tid & 31) == 0) red[tid >> 5] = v;
    __syncthreads();
    if (tid == 0) {
        float s = red[0];
        #pragma unroll
        for (int i = 1; i < 8; i++) s += red[i];
        red[0] = s;
    }
    __syncthreads();
    float r = red[0];
    __syncthreads();
    return r;
}

__device__ __forceinline__ float blockReduceMax256(float v, float* red) {
    #pragma unroll
    for (int o = 16; o; o >>= 1) v = fmaxf(v, __shfl_down_sync(0xffffffffu, v, o));
    int tid = threadIdx.x;
    if ((tid & 31) == 0) red[tid >> 5] = v;
    __syncthreads();
    if (tid == 0) {
        float s = red[0];
        #pragma unroll
        for (int i = 1; i < 8; i++) s = fmaxf(s, red[i]);
        red[0] = s;
    }
    __syncthreads();
    float r = red[0];
    __syncthreads();
    return r;
}

__device__ __forceinline__ float blockReduceSum1024(float v, float* red) {
    #pragma unroll
    for (int o = 16; o; o >>= 1) v += __shfl_down_sync(0xffffffffu, v, o);
    int tid = threadIdx.x;
    if ((tid & 31) == 0) red[tid >> 5] = v;
    __syncthreads();
    if (tid == 0) {
        float s = red[0];
        #pragma unroll
        for (int i = 1; i < 32; i++) s += red[i];
        red[0] = s;
    }
    __syncthreads();
    float r = red[0];
    __syncthreads();
    return r;
}

// ---------------- embed + ln1(layer 0) ----------------
__global__ void embed_kernel(const int* __restrict__ ids,
                             const float* __restrict__ wte,
                             const float* __restrict__ wpe,
                             const float* __restrict__ lw,
                             const float* __restrict__ lb) {
    __shared__ float red[8];
    int b = blockIdx.x, tid = threadIdx.x;   // 256 threads, one float4 each
    int id = ids[b * SS + (SS - 1)];
    float4 v = ((const float4*)(wte + (size_t)id * EE))[tid];
    float4 p = ((const float4*)(wpe + (size_t)(SS - 1) * EE))[tid];
    v.x += p.x; v.y += p.y; v.z += p.z; v.w += p.w;
    ((float4*)g_h)[b * 256 + tid] = v;
    float ls = v.x + v.y + v.z + v.w;
    float mean = blockReduceSum256(ls, red) * (1.f / EE);
    float dx = v.x - mean, dy = v.y - mean, dz = v.z - mean, dw = v.w - mean;
    ls = dx * dx + dy * dy + dz * dz + dw * dw;
    float rstd = rsqrtf(blockReduceSum256(ls, red) * (1.f / EE) + 1e-5f);
    float4 w4 = ((const float4*)lw)[tid];
    float4 b4 = ((const float4*)lb)[tid];
    float4 o;
    o.x = dx * rstd * w4.x + b4.x;
    o.y = dy * rstd * w4.y + b4.y;
    o.z = dz * rstd * w4.z + b4.z;
    o.w = dw * rstd * w4.w + b4.w;
    ((float4*)g_x)[b * 256 + tid] = o;
}

// ---------------- GEMV core: 256 thr = 32 float4 cols x 8 K-sub-slices ----------------
// Maximizes distinct-address warp streams (the measured per-warp DRAM BW lever).
// smem tree-combine over the 8 K-sub accumulators; one partial write per split.
template<int KCB, int N>
__device__ __forceinline__ void gemv_core4(const float* xs,
                                           const float* __restrict__ W,
                                           float* __restrict__ part) {
    constexpr int KSUB = 8, CPB = 32;
    constexpr int KH = KCB / KSUB;
    int tid = threadIdx.x;
    int col = tid & 31, ksub = tid >> 5;
    int n4 = blockIdx.x * CPB + col;
    int sp = blockIdx.y;
    const float4* wp = ((const float4*)W) + (size_t)(sp * KCB + ksub * KH) * (N / 4) + n4;
    const float* xk = xs + ksub * KH;
    float4 acc[8];
    #pragma unroll
    for (int b = 0; b < 8; b++) { acc[b].x = 0.f; acc[b].y = 0.f; acc[b].z = 0.f; acc[b].w = 0.f; }
    #pragma unroll
    for (int k = 0; k < KH; k++) {
        float4 wv = wp[(size_t)k * (N / 4)];
        #pragma unroll
        for (int b = 0; b < 8; b++) {
            float xv = xk[b * KCB + k];
            acc[b].x = fmaf(xv, wv.x, acc[b].x);
            acc[b].y = fmaf(xv, wv.y, acc[b].y);
            acc[b].z = fmaf(xv, wv.z, acc[b].z);
            acc[b].w = fmaf(xv, wv.w, acc[b].w);
        }
    }
    __shared__ __align__(16) float4 cmb[KSUB][8][CPB];   // 32KB
    #pragma unroll
    for (int b = 0; b < 8; b++) cmb[ksub][b][col] = acc[b];
    __syncthreads();
    // remap: 256 threads = 8 batches x 32 cols; sum the 8 K-subs
    int b = tid >> 5, c = tid & 31;
    float4 o = cmb[0][b][c];
    #pragma unroll
    for (int ks = 1; ks < KSUB; ks++) {
        float4 q = cmb[ks][b][c];
        o.x += q.x; o.y += q.y; o.z += q.z; o.w += q.w;
    }
    ((float4*)part)[(size_t)(sp * 8 + b) * (N / 4) + blockIdx.x * CPB + c] = o;
}

// plain: input = g_x, output = scratch_buf<DST>
template<int KCB, int N, int K, int DST>
__global__ void __launch_bounds__(256) gemv_k(const float* __restrict__ W) {
    __shared__ float xs[8 * KCB];
    int tid = threadIdx.x;
    int k0 = blockIdx.y * KCB;
    if (tid < 8 * KCB) {
        int b = tid / KCB, k = tid % KCB;
        xs[tid] = g_x[b * K + k0 + k];
    }
    __syncthreads();
    gemv_core4<KCB, N>(xs, W, scratch_buf<DST>());
}

// gelu: input = sum of fc partials + bias, gelu'd  (K = FF)
template<int KCB, int N, int DST>
__global__ void __launch_bounds__(256) gemv_gelu_k(const float* __restrict__ fcb,
                                                   const float* __restrict__ W) {
    __shared__ float xs[8 * KCB];
    int tid = threadIdx.x;
    int k0 = blockIdx.y * KCB;
    if (tid < 8 * KCB) {
        int b = tid / KCB, k = k0 + tid % KCB;
        float v = fcb[k];
        #pragma unroll 16
        for (int s = 0; s < FS; s++) v += g_fc[(size_t)(s * 8 + b) * FF + k];
        float c3 = v * v * v;
        xs[tid] = 0.5f * v * (1.f + tanhf(0.7978845608028654f * (v + 0.044715f * c3)));
    }
    __syncthreads();
    gemv_core4<KCB, N>(xs, W, scratch_buf<DST>());
}

// ctx: input built from attention partials (flash-decode combine), K = EE
template<int KCB, int N, int DST>
__global__ void __launch_bounds__(256) gemv_ctx_k(const float* __restrict__ W) {
    __shared__ float xs[8 * KCB];
    int tid = threadIdx.x;
    int k0 = blockIdx.y * KCB;
    if (tid < 8 * KCB) {
        int b = tid / KCB;
        int kg = k0 + tid % KCB;
        int head = kg >> 6, d = kg & 63;
        int bh = b * HH + head;
        const float* ap = &g_ap[(size_t)bh * TS * 66];
        float gm = -1e30f;
        #pragma unroll
        for (int ts = 0; ts < TS; ts++) gm = fmaxf(gm, ap[ts * 66]);
        float den = 0.f, val = 0.f;
        #pragma unroll
        for (int ts = 0; ts < TS; ts++) {
            float e = __expf(ap[ts * 66] - gm);
            den += ap[ts * 66 + 1] * e;
            val += ap[ts * 66 + 2 + d] * e;
        }
        xs[tid] = val / den;
    }
    __syncthreads();
    gemv_core4<KCB, N>(xs, W, scratch_buf<DST>());
}

// ---------------- attention: fused qkv combine + register-resident two-pass ----------------
__global__ void __launch_bounds__(256, 2) attn_kernel(const float* __restrict__ kc,
                                                      const float* __restrict__ vc,
                                                      const float* __restrict__ cab,
                                                      const float* __restrict__ abp) {
    __shared__ __align__(16) float qs[DD], kn[DD], vn[DD];
    __shared__ float gm_s[16], gd_s[16];
    __shared__ __align__(16) float gacc[16][DD];
    int tid = threadIdx.x;
    int bh = blockIdx.x;
    int b = bh >> 4, h = bh & 15;
    int ts = blockIdx.y;

    // fused qkv split-combine for this (b, head): 192 values (q, k_new, v_new)
    if (tid < 192) {
        int grp = tid >> 6;         // 0:q 1:k 2:v
        int d = tid & 63;
        int j = grp * EE + h * DD + d;
        float v = cab[j];
        #pragma unroll 16
        for (int s = 0; s < QS; s++) v += g_qkv[(size_t)(s * 8 + b) * (3 * EE) + j];
        if (grp == 0) qs[d] = v; else if (grp == 1) kn[d] = v; else vn[d] = v;
    }
    __syncthreads();

    int w = tid >> 5, lane = tid & 31;
    int half = lane >> 4, sub = lane & 15;
    int g = w * 2 + half;                 // 16 lane-groups of 16
    float4 qv = ((const float4*)qs)[sub];
    const float4* knp = (const float4*)kn;
    const float4* vnp = (const float4*)vn;
    size_t rowbase = (size_t)(b * HH + h) * TT;
    int t0 = ts * 128;
    float abias = abp[0];

    // issue all 16 independent LDG.128 before any math
    float4 kk[8], vv[8];
    #pragma unroll
    for (int j = 0; j < 8; j++) {
        int t = t0 + j * 16 + g;
        const float4* kr = (t < TT) ? (const float4*)(kc + (rowbase + t) * DD) : knp;
        kk[j] = kr[sub];
    }
    #pragma unroll
    for (int j = 0; j < 8; j++) {
        int t = t0 + j * 16 + g;
        const float4* vr = (t < TT) ? (const float4*)(vc + (rowbase + t) * DD) : vnp;
        vv[j] = vr[sub];
    }

    float p[8];
    #pragma unroll
    for (int j = 0; j < 8; j++) {
        float s = kk[j].x * qv.x + kk[j].y * qv.y + kk[j].z * qv.z + kk[j].w * qv.w;
        s += __shfl_xor_sync(0xffffffffu, s, 8);
        s += __shfl_xor_sync(0xffffffffu, s, 4);
        s += __shfl_xor_sync(0xffffffffu, s, 2);
        s += __shfl_xor_sync(0xffffffffu, s, 1);
        p[j] = s * 0.125f + abias;
    }
    float m = p[0];
    #pragma unroll
    for (int j = 1; j < 8; j++) m = fmaxf(m, p[j]);
    float den = 0.f;
    float4 acc; acc.x = acc.y = acc.z = acc.w = 0.f;
    #pragma unroll
    for (int j = 0; j < 8; j++) {
        float e = __expf(p[j] - m);
        den += e;
        acc.x = fmaf(e, vv[j].x, acc.x);
        acc.y = fmaf(e, vv[j].y, acc.y);
        acc.z = fmaf(e, vv[j].z, acc.z);
        acc.w = fmaf(e, vv[j].w, acc.w);
    }

    if (sub == 0) { gm_s[g] = m; gd_s[g] = den; }
    ((float4*)gacc[g])[sub] = acc;
    __syncthreads();

    if (tid < DD) {
        float gm = -1e30f;
        #pragma unroll
        for (int g2 = 0; g2 < 16; g2++) gm = fmaxf(gm, gm_s[g2]);
        float dd = 0.f, val = 0.f;
        #pragma unroll
        for (int g2 = 0; g2 < 16; g2++) {
            float e = __expf(gm_s[g2] - gm);
            dd += gd_s[g2] * e;
            val += gacc[g2][tid] * e;
        }
        float* ap = &g_ap[((size_t)bh * TS + ts) * 66];
        if (tid == 0) { ap[0] = gm; ap[1] = dd; }
        ap[2 + tid] = val;
    }
}

// ---------------- residual (sum split partials + bias) + layernorm -> g_x ----------------
template<int SRC, int NS>
__global__ void __launch_bounds__(1024) resid_ln_kernel(const float* __restrict__ bias,
                                                        const float* __restrict__ lw,
                                                        const float* __restrict__ lb) {
    __shared__ __align__(16) float4 ps[4][256];
    __shared__ float red[32];
    const float4* part = (const float4*)scratch_buf<SRC>();
    int b = blockIdx.x, tid = threadIdx.x;
    int c = tid & 255, grp = tid >> 8;
    float4 v; v.x = v.y = v.z = v.w = 0.f;
    #pragma unroll 16
    for (int sp = grp; sp < NS; sp += 4) {
        float4 p = part[(size_t)(sp * 8 + b) * 256 + c];
        v.x += p.x; v.y += p.y; v.z += p.z; v.w += p.w;
    }
    ps[grp][c] = v;
    __syncthreads();
    float4 hv; hv.x = hv.y = hv.z = hv.w = 0.f;
    if (grp == 0) {
        float4 h4 = ((const float4*)g_h)[b * 256 + c];
        float4 bv = ((const float4*)bias)[c];
        float4 s1 = ps[1][c], s2 = ps[2][c], s3 = ps[3][c];
        hv.x = v.x + s1.x + s2.x + s3.x + h4.x + bv.x;
        hv.y = v.y + s1.y + s2.y + s3.y + h4.y + bv.y;
        hv.z = v.z + s1.z + s2.z + s3.z + h4.z + bv.z;
        hv.w = v.w + s1.w + s2.w + s3.w + h4.w + bv.w;
        ((float4*)g_h)[b * 256 + c] = hv;
    }
    float ls = (grp == 0) ? (hv.x + hv.y + hv.z + hv.w) : 0.f;
    float mean = blockReduceSum1024(ls, red) * (1.f / EE);
    float dx = hv.x - mean, dy = hv.y - mean, dz = hv.z - mean, dw = hv.w - mean;
    ls = (grp == 0) ? (dx * dx + dy * dy + dz * dz + dw * dw) : 0.f;
    float rstd = rsqrtf(blockReduceSum1024(ls, red) * (1.f / EE) + 1e-5f);
    if (grp == 0) {
        float4 w4 = ((const float4*)lw)[c];
        float4 b4 = ((const float4*)lb)[c];
        float4 o;
        o.x = dx * rstd * w4.x + b4.x;
        o.y = dy * rstd * w4.y + b4.y;
        o.z = dz * rstd * w4.z + b4.z;
        o.w = dw * rstd * w4.w + b4.w;
        ((float4*)g_x)[b * 256 + c] = o;
    }
}

// ---------------- logits: 4 vocab rows per warp (one quad each), 8-batch reuse ----------------
__global__ void __launch_bounds__(256) logits_kernel(const float* __restrict__ wte) {
    __shared__ __align__(16) float4 xs[8][256];
    int tid = threadIdx.x;
    for (int i = tid; i < 2048; i += 256) {
        int b = i >> 8, j = i & 255;
        xs[b][j] = ((const float4*)g_x)[b * 256 + j];
    }
    __syncthreads();
    int gw = blockIdx.x * 8 + (tid >> 5);
    int lane = tid & 31;
    int v0 = gw * 4;
    if (v0 >= VV) return;
    const float4* r0 = (const float4*)(wte + (size_t)v0 * EE);
    const float4* r1 = (const float4*)(wte + (size_t)((v0 + 1 < VV) ? v0 + 1 : v0) * EE);
    const float4* r2 = (const float4*)(wte + (size_t)((v0 + 2 < VV) ? v0 + 2 : v0) * EE);
    const float4* r3 = (const float4*)(wte + (size_t)((v0 + 3 < VV) ? v0 + 3 : v0) * EE);
    float a0[8], a1[8], a2[8], a3[8];
    #pragma unroll
    for (int b = 0; b < 8; b++) { a0[b] = a1[b] = a2[b] = a3[b] = 0.f; }
    #pragma unroll
    for (int i = 0; i < 8; i++) {
        int idx = lane + 32 * i;
        float4 w0 = r0[idx], w1 = r1[idx], w2 = r2[idx], w3 = r3[idx];
        #pragma unroll
        for (int b = 0; b < 8; b++) {
            float4 xb = xs[b][idx];
            a0[b] += w0.x * xb.x + w0.y * xb.y + w0.z * xb.z + w0.w * xb.w;
            a1[b] += w1.x * xb.x + w1.y * xb.y + w1.z * xb.z + w1.w * xb.w;
            a2[b] += w2.x * xb.x + w2.y * xb.y + w2.z * xb.z + w2.w * xb.w;
            a3[b] += w3.x * xb.x + w3.y * xb.y + w3.z * xb.z + w3.w * xb.w;
        }
    }
    #pragma unroll
    for (int b = 0; b < 8; b++) {
        #pragma unroll
        for (int o = 16; o; o >>= 1) {
            a0[b] += __shfl_down_sync(0xffffffffu, a0[b], o);
            a1[b] += __shfl_down_sync(0xffffffffu, a1[b], o);
            a2[b] += __shfl_down_sync(0xffffffffu, a2[b], o);
            a3[b] += __shfl_down_sync(0xffffffffu, a3[b], o);
        }
    }
    if (lane == 0) {
        #pragma unroll
        for (int b = 0; b < 8; b++) {
            g_logits[(size_t)b * VV + v0] = a0[b];
            if (v0 + 1 < VV) g_logits[(size_t)b * VV + v0 + 1] = a1[b];
            if (v0 + 2 < VV) g_logits[(size_t)b * VV + v0 + 2] = a2[b];
            if (v0 + 3 < VV) g_logits[(size_t)b * VV + v0 + 3] = a3[b];
        }
    }
}

// ---------------- softmax: partial stats over 32 chunks/batch, combined in norm ----------------
#define CH ((VV + NCH - 1) / NCH)   // 1571
__global__ void __launch_bounds__(256) softmax_pstats_kernel() {
    __shared__ float red[8];
    int b = blockIdx.x, ch = blockIdx.y, tid = threadIdx.x;
    int start = ch * CH;
    int end = (start + CH < VV) ? start + CH : VV;
    const float* lg = g_logits + (size_t)b * VV;
    float m = -1e30f;
    #pragma unroll 4
    for (int v = start + tid; v < end; v += 256) m = fmaxf(m, lg[v]);
    m = blockReduceMax256(m, red);
    float s = 0.f;
    #pragma unroll 4
    for (int v = start + tid; v < end; v += 256) s += __expf(lg[v] - m);
    s = blockReduceSum256(s, red);
    if (tid == 0) { g_pstats[b][ch][0] = m; g_pstats[b][ch][1] = s; }
}

__global__ void __launch_bounds__(256) softmax_norm_kernel(float* __restrict__ out) {
    __shared__ float sm, ss;
    int i = blockIdx.x * 256 + threadIdx.x;
    int b = (blockIdx.x * 256) / VV;
    if (threadIdx.x < 32) {
        float m = g_pstats[b][threadIdx.x][0];
        #pragma unroll
        for (int o = 16; o; o >>= 1) m = fmaxf(m, __shfl_xor_sync(0xffffffffu, m, o));
        float s = g_pstats[b][threadIdx.x][1] * __expf(g_pstats[b][threadIdx.x][0] - m);
        #pragma unroll
        for (int o = 16; o; o >>= 1) s += __shfl_xor_sync(0xffffffffu, s, o);
        if (threadIdx.x == 0) { sm = m; ss = s; }
    }
    __syncthreads();
    if (i < BB * VV) {
        int be = i / VV;
        float m, s;
        if (be == b) { m = sm; s = ss; }
        else {
            m = -1e30f;
            #pragma unroll
            for (int c = 0; c < NCH; c++) m = fmaxf(m, g_pstats[be][c][0]);
            s = 0.f;
            #pragma unroll
            for (int c = 0; c < NCH; c++) s += g_pstats[be][c][1] * __expf(g_pstats[be][c][0] - m);
        }
        out[i] = __expf(g_logits[i] - m) * (1.f / s);
    }
}

// ---------------- launch ----------------
extern "C" void kernel_launch(void* const* d_in, const int* in_sizes, int n_in,
                              void* d_out, int out_size) {
    const int*   ids  = (const int*)  d_in[0];
    const float* kc   = (const float*)d_in[1];
    const float* vc   = (const float*)d_in[2];
    const float* wte  = (const float*)d_in[3];
    const float* wpe  = (const float*)d_in[4];
    const float* l1w  = (const float*)d_in[5];
    const float* l1b  = (const float*)d_in[6];
    const float* caw  = (const float*)d_in[7];
    const float* cab  = (const float*)d_in[8];
    const float* apw  = (const float*)d_in[9];
    const float* apb  = (const float*)d_in[10];
    const float* l2w  = (const float*)d_in[11];
    const float* l2b  = (const float*)d_in[12];
    const float* fw   = (const float*)d_in[13];
    const float* fb   = (const float*)d_in[14];
    const float* pw   = (const float*)d_in[15];
    const float* pb   = (const float*)d_in[16];
    const float* lnfw = (const float*)d_in[17];
    const float* lnfb = (const float*)d_in[18];
    const float* ab   = (const float*)d_in[19];
    float* out = (float*)d_out;

    embed_kernel<<<BB, 256>>>(ids, wte, wpe, l1w, l1b);

    for (int l = 0; l < LL; l++) {
        // qkv = x @ c_attn_w  (N=3072: 24 col-blocks x 32 splits) -> 768 blocks
        gemv_k<32, 3 * EE, EE, BUF_QKV><<<dim3(24, QS), 256>>>(caw + (size_t)l * EE * 3 * EE);

        // attention (fused qkv combine): 1024 blocks
        attn_kernel<<<dim3(BB * HH, TS), 256>>>(
            kc + (size_t)l * BB * HH * TT * DD,
            vc + (size_t)l * BB * HH * TT * DD,
            cab + (size_t)l * 3 * EE,
            ab + l);

        // attn proj (combine fused): N=1024: 8 col-blocks x 64 splits -> 512 blocks
        gemv_ctx_k<16, EE, BUF_APROJ><<<dim3(8, AS), 256>>>(apw + (size_t)l * EE * EE);

        // h += attnout + apb ; x = ln2(h)
        resid_ln_kernel<BUF_APROJ, AS><<<BB, 1024>>>(apb + (size_t)l * EE,
                                                     l2w + (size_t)l * EE,
                                                     l2b + (size_t)l * EE);

        // fc = x @ fc_w  (N=4096: 32 col-blocks x 32 splits) -> 1024 blocks
        gemv_k<32, FF, EE, BUF_FC><<<dim3(32, FS), 256>>>(fw + (size_t)l * EE * FF);

        // mlp proj = gelu(fc + fb) @ pw  (N=1024: 8 col-blocks x 128 splits) -> 1024 blocks
        gemv_gelu_k<32, EE, BUF_MP><<<dim3(8, MS), 256>>>(fb + (size_t)l * FF,
                                                          pw + (size_t)l * FF * EE);

        // h += mlpout + pb ; x = ln1(h,l+1)  (or lnf at the last layer)
        const float* nlw = (l < LL - 1) ? (l1w + (size_t)(l + 1) * EE) : lnfw;
        const float* nlb = (l < LL - 1) ? (l1b + (size_t)(l + 1) * EE) : lnfb;
        resid_ln_kernel<BUF_MP, MS><<<BB, 1024>>>(pb + (size_t)l * EE, nlw, nlb);
    }

    logits_kernel<<<1571, 256>>>(wte);
    softmax_pstats_kernel<<<dim3(BB, NCH), 256>>>();
    softmax_norm_kernel<<<(BB * VV + 255) / 256, 256>>>(out);
}